// round 1
// baseline (speedup 1.0000x reference)
#include <cuda_runtime.h>
#include <cuda_bf16.h>

// Problem constants (fixed by reference)
#define NPTS 1024
#define HDIM 32

typedef unsigned long long u64;

// ---------- scratch (no allocs allowed) ----------
__device__ float g_a[NPTS * HDIM];
__device__ float g_c[(NPTS + 1) * HDIM];   // +1 row zero padding for prefetch
__device__ float g_h1[NPTS * HDIM];

// ---------- packed f32x2 helpers ----------
__device__ __forceinline__ u64 f2fma(u64 a, u64 b, u64 c) {
    u64 d;
    asm("fma.rn.f32x2 %0, %1, %2, %3;" : "=l"(d) : "l"(a), "l"(b), "l"(c));
    return d;
}
__device__ __forceinline__ u64 pack2(float lo, float hi) {
    u64 r;
    asm("mov.b64 %0, {%1, %2};" : "=l"(r) : "f"(lo), "f"(hi));
    return r;
}
__device__ __forceinline__ float hsum2(u64 v) {
    float lo, hi;
    asm("mov.b64 {%0, %1}, %2;" : "=f"(lo), "=f"(hi) : "l"(v));
    return lo + hi;
}
__device__ __forceinline__ float fast_sigmoid(float x) {
    // accurate path: EX2-based expf + fast reciprocal (~1e-6 rel err)
    float e = __expf(-x);
    return __fdividef(1.0f, 1.0f + e);
}
__device__ __forceinline__ float fast_tanh(float x) {
    // tanh(x) = 2*sigmoid(2x) - 1
    float s = fast_sigmoid(2.0f * x);
    return fmaf(2.0f, s, -1.0f);
}

// ---------- precompute: a_i = (Wa-Wb)@x_i + b ; c_j = Wb@x_j ----------
// w is (H, 2F); Wa = w[:, :F], Wb = w[:, F:2F]. One warp per row i, lane = h.
template <int F>
__global__ void __launch_bounds__(256)
pre_kernel(const float* __restrict__ x, const float* __restrict__ w,
           const float* __restrict__ b, float* __restrict__ a,
           float* __restrict__ c) {
    int wq = threadIdx.x >> 5;
    int l = threadIdx.x & 31;
    int i = blockIdx.x * 8 + wq;
    if (i >= NPTS) return;
    float av = b[l];
    float cv = 0.0f;
    const float* wr = w + l * (2 * F);
    const float* xr = x + i * F;
#pragma unroll
    for (int f = 0; f < F; ++f) {
        float xv = xr[f];
        float wa = wr[f];
        float wb = wr[F + f];
        av = fmaf(wa - wb, xv, av);
        cv = fmaf(wb, xv, cv);
    }
    a[i * HDIM + l] = av;
    c[i * HDIM + l] = cv;
}

// ---------- GRU scan: one warp per sequence i, lane = hidden unit ----------
// Per step j: u = relu(a_i + c_j); xg = Wih@u + bih; hg = Whh@h + bhh;
// r=sig(xr+hr), z=sig(xz+hz), n=tanh(xn + r*hn), h = n + z*(h-n).
// Weights held in registers as f32x2 pairs; u/h broadcast via double-buffered
// smem with one __syncwarp per step.
template <int FUSE_CLF>
__global__ void __launch_bounds__(128, 2)
gru_scan_kernel(const float* __restrict__ a, const float* __restrict__ c,
                const float* __restrict__ wih, const float* __restrict__ whh,
                const float* __restrict__ bih, const float* __restrict__ bhh,
                const float* __restrict__ clf_w, const float* __restrict__ clf_b,
                float* __restrict__ out) {
    __shared__ __align__(16) float s_u[4][2][HDIM];
    __shared__ __align__(16) float s_h[4][2][HDIM];

    const int w = threadIdx.x >> 5;
    const int l = threadIdx.x & 31;
    const int i = blockIdx.x * 4 + w;

    // Load this lane's 6 weight rows (r/z/n for ih and hh), packed pairs.
    u64 Wru[16], Wzu[16], Wnu[16], Wrh[16], Wzh[16], Wnh[16];
    {
        const u64* pr = (const u64*)(wih + (0 * HDIM + l) * HDIM);
        const u64* pz = (const u64*)(wih + (1 * HDIM + l) * HDIM);
        const u64* pn = (const u64*)(wih + (2 * HDIM + l) * HDIM);
        const u64* qr = (const u64*)(whh + (0 * HDIM + l) * HDIM);
        const u64* qz = (const u64*)(whh + (1 * HDIM + l) * HDIM);
        const u64* qn = (const u64*)(whh + (2 * HDIM + l) * HDIM);
#pragma unroll
        for (int k = 0; k < 16; ++k) {
            Wru[k] = pr[k];
            Wzu[k] = pz[k];
            Wnu[k] = pn[k];
            Wrh[k] = qr[k];
            Wzh[k] = qz[k];
            Wnh[k] = qn[k];
        }
    }

    const float b_r = bih[l] + bhh[l];            // r: x-part + h-part fused
    const float b_z = bih[HDIM + l] + bhh[HDIM + l];
    const float b_xn = bih[2 * HDIM + l];
    const float b_hn = bhh[2 * HDIM + l];

    const float a_l = a[i * HDIM + l];
    float h = 0.0f;
    float c_next = c[l];  // prefetch j=0

#pragma unroll 2
    for (int j = 0; j < NPTS; ++j) {
        float cc = c_next;
        c_next = c[(j + 1) * HDIM + l];  // row NPTS is zero padding
        float u = fmaxf(a_l + cc, 0.0f);

        const int buf = j & 1;
        s_u[w][buf][l] = u;
        s_h[w][buf][l] = h;
        __syncwarp();

        const u64* up = (const u64*)s_u[w][buf];
        const u64* hp = (const u64*)s_h[w][buf];

        u64 ar = pack2(b_r, 0.0f);
        u64 az = pack2(b_z, 0.0f);
        u64 an = pack2(b_xn, 0.0f);
        u64 ah = pack2(b_hn, 0.0f);

#pragma unroll
        for (int k = 0; k < 16; ++k) {
            u64 u2 = up[k];
            u64 h2 = hp[k];
            ar = f2fma(Wru[k], u2, ar);
            ar = f2fma(Wrh[k], h2, ar);
            az = f2fma(Wzu[k], u2, az);
            az = f2fma(Wzh[k], h2, az);
            an = f2fma(Wnu[k], u2, an);
            ah = f2fma(Wnh[k], h2, ah);
        }

        float r = fast_sigmoid(hsum2(ar));
        float z = fast_sigmoid(hsum2(az));
        float n = fast_tanh(fmaf(r, hsum2(ah), hsum2(an)));
        h = fmaf(z, h - n, n);
    }

    if (FUSE_CLF) {
        // out[i, o] = clf_b[o] + sum_h clf_w[o,h] * h[h]
        s_h[w][0][l] = h;
        __syncwarp();
        if (l < 3) {
            float acc = clf_b[l];
            const float* cw = clf_w + l * HDIM;
#pragma unroll
            for (int hh = 0; hh < HDIM; ++hh)
                acc = fmaf(cw[hh], s_h[w][0][hh], acc);
            out[i * 3 + l] = acc;
        }
    } else {
        out[i * HDIM + l] = h;
    }
}

extern "C" void kernel_launch(void* const* d_in, const int* in_sizes, int n_in,
                              void* d_out, int out_size) {
    const float* x        = (const float*)d_in[0];
    const float* proj1_w  = (const float*)d_in[1];
    const float* proj1_b  = (const float*)d_in[2];
    const float* gru1_wih = (const float*)d_in[3];
    const float* gru1_whh = (const float*)d_in[4];
    const float* gru1_bih = (const float*)d_in[5];
    const float* gru1_bhh = (const float*)d_in[6];
    const float* proj2_w  = (const float*)d_in[7];
    const float* proj2_b  = (const float*)d_in[8];
    const float* gru2_wih = (const float*)d_in[9];
    const float* gru2_whh = (const float*)d_in[10];
    const float* gru2_bih = (const float*)d_in[11];
    const float* gru2_bhh = (const float*)d_in[12];
    const float* clf_w    = (const float*)d_in[13];
    const float* clf_b    = (const float*)d_in[14];
    float* out = (float*)d_out;

    float *pa, *pc, *ph1;
    cudaGetSymbolAddress((void**)&pa, g_a);
    cudaGetSymbolAddress((void**)&pc, g_c);
    cudaGetSymbolAddress((void**)&ph1, g_h1);

    // Stage 1
    pre_kernel<16><<<128, 256>>>(x, proj1_w, proj1_b, pa, pc);
    gru_scan_kernel<0><<<256, 128>>>(pa, pc, gru1_wih, gru1_whh, gru1_bih,
                                     gru1_bhh, nullptr, nullptr, ph1);
    // Stage 2 (reuse a/c scratch) + fused classifier
    pre_kernel<32><<<128, 256>>>(ph1, proj2_w, proj2_b, pa, pc);
    gru_scan_kernel<1><<<256, 128>>>(pa, pc, gru2_wih, gru2_whh, gru2_bih,
                                     gru2_bhh, clf_w, clf_b, out);
}

// round 3
// speedup vs baseline: 1.0574x; 1.0574x over previous
#include <cuda_runtime.h>
#include <cuda_bf16.h>
#include <cstdint>

#define NPTS 1024
#define HDIM 32

typedef unsigned long long u64;
typedef unsigned int u32;

// ---------- scratch ----------
__device__ float g_a[NPTS * HDIM];
__device__ float g_c[(NPTS + 1) * HDIM];   // row NPTS stays zero (prefetch pad)
__device__ float g_h1[NPTS * HDIM];

// ---------- packed f32x2 helpers ----------
__device__ __forceinline__ u64 f2fma(u64 a, u64 b, u64 c) {
    u64 d;
    asm("fma.rn.f32x2 %0, %1, %2, %3;" : "=l"(d) : "l"(a), "l"(b), "l"(c));
    return d;
}
__device__ __forceinline__ u64 add2(u64 a, u64 b) {
    u64 d;
    asm("add.rn.f32x2 %0, %1, %2;" : "=l"(d) : "l"(a), "l"(b));
    return d;
}
__device__ __forceinline__ u64 pack2(float lo, float hi) {
    u64 r;
    asm("mov.b64 %0, {%1, %2};" : "=l"(r) : "f"(lo), "f"(hi));
    return r;
}
__device__ __forceinline__ void unpack2(float& lo, float& hi, u64 v) {
    asm("mov.b64 {%0, %1}, %2;" : "=f"(lo), "=f"(hi) : "l"(v));
}
__device__ __forceinline__ float hsum2(u64 v) {
    float lo, hi;
    unpack2(lo, hi, v);
    return lo + hi;
}
__device__ __forceinline__ float tanh_hw(float x) {
    float y;
    asm("tanh.approx.f32 %0, %1;" : "=f"(y) : "f"(x));
    return y;
}
__device__ __forceinline__ float sig_hw(float x) {
    return fmaf(tanh_hw(0.5f * x), 0.5f, 0.5f);
}
__device__ __forceinline__ u32 smem_u32(const void* p) {
    u32 a;
    asm("{ .reg .u64 t; cvta.to.shared.u64 t, %1; cvt.u32.u64 %0, t; }"
        : "=r"(a) : "l"(p));
    return a;
}
__device__ __forceinline__ void sts64(u32 addr, u64 v) {
    asm volatile("st.shared.b64 [%0], %1;" :: "r"(addr), "l"(v) : "memory");
}
__device__ __forceinline__ void lds_v2(u64& p0, u64& p1, u32 addr) {
    asm volatile("ld.shared.v2.u64 {%0, %1}, [%2];"
                 : "=l"(p0), "=l"(p1) : "r"(addr));
}

// ---------- precompute: a_i = (Wa-Wb)@x_i + b ; c_j = Wb@x_j ----------
template <int F>
__global__ void __launch_bounds__(256)
pre_kernel(const float* __restrict__ x, const float* __restrict__ w,
           const float* __restrict__ b, float* __restrict__ a,
           float* __restrict__ c) {
    int wq = threadIdx.x >> 5;
    int l = threadIdx.x & 31;
    int i = blockIdx.x * 8 + wq;
    if (i >= NPTS) return;
    float av = b[l];
    float cv = 0.0f;
    const float* wr = w + l * (2 * F);
    const float* xr = x + i * F;
#pragma unroll
    for (int f = 0; f < F; ++f) {
        float xv = xr[f];
        float wa = wr[f];
        float wb = wr[F + f];
        av = fmaf(wa - wb, xv, av);
        cv = fmaf(wb, xv, cv);
    }
    a[i * HDIM + l] = av;
    c[i * HDIM + l] = cv;
}

// ---------- GRU scan: one warp per sequence, lane = hidden unit ----------
// Paired form: v_k = (u_k, h_k); weight pairs Wg[k] = (Wih[g,l,k], Whh[g,l,k]).
// f2fma accumulates (x-part, h-part) in lo/hi; r,z sum both halves, n keeps
// them separate (n = tanh(xn + r*hn)).
template <int FUSE_CLF>
__global__ void __launch_bounds__(64, 4)
gru_scan_kernel(const float* __restrict__ a, const float* __restrict__ c,
                const float* __restrict__ wih, const float* __restrict__ whh,
                const float* __restrict__ bih, const float* __restrict__ bhh,
                const float* __restrict__ clf_w, const float* __restrict__ clf_b,
                float* __restrict__ out) {
    __shared__ __align__(16) float2 s_v[2][2][HDIM];   // [warp][buf][lane]

    const int w = threadIdx.x >> 5;
    const int l = threadIdx.x & 31;
    const int i = blockIdx.x * 2 + w;

    // Interleaved weight pairs, 96 u64 in registers.
    u64 Wr[32], Wz[32], Wn[32];
    {
        const float* pr = wih + (0 * HDIM + l) * HDIM;
        const float* pz = wih + (1 * HDIM + l) * HDIM;
        const float* pn = wih + (2 * HDIM + l) * HDIM;
        const float* qr = whh + (0 * HDIM + l) * HDIM;
        const float* qz = whh + (1 * HDIM + l) * HDIM;
        const float* qn = whh + (2 * HDIM + l) * HDIM;
#pragma unroll
        for (int k = 0; k < HDIM; ++k) {
            Wr[k] = pack2(pr[k], qr[k]);
            Wz[k] = pack2(pz[k], qz[k]);
            Wn[k] = pack2(pn[k], qn[k]);
        }
    }

    const float b_r = bih[l] + bhh[l];
    const float b_z = bih[HDIM + l] + bhh[HDIM + l];
    const float b_xn = bih[2 * HDIM + l];
    const float b_hn = bhh[2 * HDIM + l];
    const u64 init_r = pack2(b_r, 0.0f);
    const u64 init_z = pack2(b_z, 0.0f);
    const u64 init_n = pack2(b_xn, b_hn);

    const float a_l = a[i * HDIM + l];
    const u32 sbase = smem_u32(&s_v[w][0][0]);

    float h = 0.0f;
    float c_next = c[l];

#pragma unroll 2
    for (int j = 0; j < NPTS; ++j) {
        const float cc = c_next;
        c_next = c[(j + 1) * HDIM + l];
        const float u = fmaxf(a_l + cc, 0.0f);

        const u32 boff = (j & 1) ? 256u : 0u;
        sts64(sbase + boff + l * 8, pack2(u, h));
        __syncwarp();

        u64 ar0 = init_r, ar1 = 0ULL;
        u64 az0 = init_z, az1 = 0ULL;
        u64 an0 = init_n, an1 = 0ULL;
        const u32 va = sbase + boff;
#pragma unroll
        for (int q = 0; q < 16; ++q) {
            u64 p0, p1;
            lds_v2(p0, p1, va + q * 16);
            ar0 = f2fma(Wr[2 * q], p0, ar0);
            ar1 = f2fma(Wr[2 * q + 1], p1, ar1);
            az0 = f2fma(Wz[2 * q], p0, az0);
            az1 = f2fma(Wz[2 * q + 1], p1, az1);
            an0 = f2fma(Wn[2 * q], p0, an0);
            an1 = f2fma(Wn[2 * q + 1], p1, an1);
        }

        const float r = sig_hw(hsum2(add2(ar0, ar1)));
        const float z = sig_hw(hsum2(add2(az0, az1)));
        float xn, hn;
        unpack2(xn, hn, add2(an0, an1));
        const float n = tanh_hw(fmaf(r, hn, xn));
        h = fmaf(z, h - n, n);
    }

    if (FUSE_CLF) {
        s_v[w][0][l] = make_float2(h, h);
        __syncwarp();
        if (l < 3) {
            float acc = clf_b[l];
            const float* cw = clf_w + l * HDIM;
#pragma unroll
            for (int hh = 0; hh < HDIM; ++hh)
                acc = fmaf(cw[hh], s_v[w][0][hh].x, acc);
            out[i * 3 + l] = acc;
        }
    } else {
        out[i * HDIM + l] = h;
    }
}

extern "C" void kernel_launch(void* const* d_in, const int* in_sizes, int n_in,
                              void* d_out, int out_size) {
    const float* x        = (const float*)d_in[0];
    const float* proj1_w  = (const float*)d_in[1];
    const float* proj1_b  = (const float*)d_in[2];
    const float* gru1_wih = (const float*)d_in[3];
    const float* gru1_whh = (const float*)d_in[4];
    const float* gru1_bih = (const float*)d_in[5];
    const float* gru1_bhh = (const float*)d_in[6];
    const float* proj2_w  = (const float*)d_in[7];
    const float* proj2_b  = (const float*)d_in[8];
    const float* gru2_wih = (const float*)d_in[9];
    const float* gru2_whh = (const float*)d_in[10];
    const float* gru2_bih = (const float*)d_in[11];
    const float* gru2_bhh = (const float*)d_in[12];
    const float* clf_w    = (const float*)d_in[13];
    const float* clf_b    = (const float*)d_in[14];
    float* out = (float*)d_out;

    float *pa, *pc, *ph1;
    cudaGetSymbolAddress((void**)&pa, g_a);
    cudaGetSymbolAddress((void**)&pc, g_c);
    cudaGetSymbolAddress((void**)&ph1, g_h1);

    pre_kernel<16><<<128, 256>>>(x, proj1_w, proj1_b, pa, pc);
    gru_scan_kernel<0><<<512, 64>>>(pa, pc, gru1_wih, gru1_whh, gru1_bih,
                                    gru1_bhh, nullptr, nullptr, ph1);
    pre_kernel<32><<<128, 256>>>(ph1, proj2_w, proj2_b, pa, pc);
    gru_scan_kernel<1><<<512, 64>>>(pa, pc, gru2_wih, gru2_whh, gru2_bih,
                                    gru2_bhh, clf_w, clf_b, out);
}